// round 14
// baseline (speedup 1.0000x reference)
#include <cuda_runtime.h>
#include <stdint.h>

// =============================================================================
// key32 = int32-wrapped reference key: (b&3)<<30 | x<<20 | y<<10 | z.
// Packed hash entry (8B): key32<<32 | index. atomicMin == min-index per key.
// EMPTY 0xFF..F unreachable (key bit 29 always 0 for coords < 512).
//
// R13: interleaved dual probe state machines (build: mask+ds per thread;
// row: mask-probe + speculative ds-probe) to double memory-level parallelism
// on the latency-bound phases. feat templated on VC=16 (shifts, no division).
// =============================================================================

#define MASK_CAP (1u << 22)
#define DS_CAP   (1u << 19)
#define EMPTY64  0xFFFFFFFFFFFFFFFFull

__device__ unsigned long long g_mtab[MASK_CAP];
__device__ unsigned long long g_dtab[DS_CAP];
__device__ float4             g_rowinfo[1100000];   // (s0, s1, attn, attn*s1)

__device__ __forceinline__ uint32_t key32_of(int4 c) {
    return ((uint32_t)c.x << 30) | ((uint32_t)c.y << 20) |
           ((uint32_t)c.z << 10) | (uint32_t)c.w;
}

__device__ __forceinline__ uint32_t hash32(uint32_t k) {
    k ^= k >> 16; k *= 0x85ebca6bu;
    k ^= k >> 13; k *= 0xc2b2ae35u;
    k ^= k >> 16;
    return k;
}

__global__ void clear_all(float* __restrict__ dsm, int Nd) {
    int t = blockIdx.x * blockDim.x + threadIdx.x;
    int stride = gridDim.x * blockDim.x;
    ulonglong2 ff = make_ulonglong2(EMPTY64, EMPTY64);
    for (int s = t; s < (int)(MASK_CAP / 2); s += stride)
        ((ulonglong2*)g_mtab)[s] = ff;
    for (int s = t; s < (int)(DS_CAP / 2); s += stride)
        ((ulonglong2*)g_dtab)[s] = ff;
    float4 z = make_float4(0.f, 0.f, 0.f, 0.f);
    for (int s = t; s < Nd / 4; s += stride)
        ((float4*)dsm)[s] = z;
    int tail = (Nd / 4) * 4;
    if (t < Nd - tail) dsm[tail + t] = 0.f;
}

// ---------------- Build: TWO interleaved insert chains per thread ----------
__global__ void build_all(const int4* __restrict__ mask_coords, int M,
                          const int4* __restrict__ ds_coords, int Nd) {
    int i = blockIdx.x * blockDim.x + threadIdx.x;
    bool do_m = (i < M);
    bool do_d = (i < Nd);
    uint32_t k1 = 0, k2 = 0, s1 = 0, s2 = 0;
    unsigned long long w1 = 0, w2 = 0;
    if (do_m) {
        k1 = key32_of(mask_coords[i]);
        s1 = hash32(k1) & (MASK_CAP - 1);
        w1 = ((unsigned long long)k1 << 32) | (uint32_t)i;
    }
    if (do_d) {
        k2 = key32_of(ds_coords[i]);
        s2 = hash32(k2) & (DS_CAP - 1);
        w2 = ((unsigned long long)k2 << 32) | (uint32_t)i;
    }
    while (do_m || do_d) {
        unsigned long long p1 = 0, p2 = 0;
        if (do_m) p1 = atomicCAS(&g_mtab[s1], EMPTY64, w1);  // both atomics
        if (do_d) p2 = atomicCAS(&g_dtab[s2], EMPTY64, w2);  // in flight
        if (do_m) {
            if (p1 == EMPTY64) do_m = false;
            else if ((uint32_t)(p1 >> 32) == k1) { atomicMin(&g_mtab[s1], w1); do_m = false; }
            else s1 = (s1 + 1) & (MASK_CAP - 1);
        }
        if (do_d) {
            if (p2 == EMPTY64) do_d = false;
            else if ((uint32_t)(p2 >> 32) == k2) { atomicMin(&g_dtab[s2], w2); do_d = false; }
            else s2 = (s2 + 1) & (DS_CAP - 1);
        }
    }
}

// ---------------- Row: interleaved mask-probe + speculative ds-probe -------
__global__ void row_kernel(const int4* __restrict__ x_coords,
                           const float2* __restrict__ mask_scores,
                           float* __restrict__ ds_mask,
                           int N) {
    int i = blockIdx.x * blockDim.x + threadIdx.x;
    if (i >= N) return;
    int4 c = x_coords[i];
    uint32_t k  = key32_of(c);
    uint32_t pk = key32_of(make_int4(c.x, c.y >> 1, c.z >> 1, c.w >> 1));
    uint32_t slot = hash32(k)  & (MASK_CAP - 1);
    uint32_t ds   = hash32(pk) & (DS_CAP - 1);
    int mi = -1, di = -1;
    bool do_m = true, do_d = true;
    while (do_m || do_d) {
        unsigned long long e1 = 0, e2 = 0;
        if (do_m) e1 = __ldg(&g_mtab[slot]);   // both loads in flight
        if (do_d) e2 = __ldg(&g_dtab[ds]);
        if (do_m) {
            if ((uint32_t)(e1 >> 32) == k) { mi = (int)(uint32_t)e1; do_m = false; }
            else if (e1 == EMPTY64) do_m = false;
            else slot = (slot + 1) & (MASK_CAP - 1);
        }
        if (do_d) {
            if ((uint32_t)(e2 >> 32) == pk) { di = (int)(uint32_t)e2; do_d = false; }
            else if (e2 == EMPTY64) do_d = false;
            else ds = (ds + 1) & (DS_CAP - 1);
        }
    }
    float s0 = 0.0f, s1 = 0.0f;
    if (mi >= 0) {
        float2 msv = __ldg(&mask_scores[mi]);
        s0 = msv.x; s1 = msv.y;
    }
    float attn = (s1 > 0.5f) ? 1.0f : 0.0f;
    g_rowinfo[i] = make_float4(s0, s1, attn, s1 * attn);
    if (attn > 0.0f && di >= 0) ds_mask[di] = 1.0f;
}

// ---------------- Feature kernel: templated VC (shifts, no division) -------
template <int VCC>
__global__ void feat_kernel_t(const float4* __restrict__ x_feats,
                              float4* __restrict__ pruned,
                              float4* __restrict__ scaled,
                              float* __restrict__ merged,
                              long long total, int C) {
    long long t = (long long)blockIdx.x * blockDim.x + threadIdx.x;
    if (t >= total) return;
    int i = (int)(t / VCC);
    int j = (int)(t % VCC);
    float4 f = x_feats[t];
    float4 rs = g_rowinfo[i];   // (s0, s1, attn, attn*s1)
    pruned[t] = make_float4(f.x * rs.z, f.y * rs.z, f.z * rs.z, f.w * rs.z);
    scaled[t] = make_float4(f.x * rs.w, f.y * rs.w, f.z * rs.w, f.w * rs.w);
    float* mrow = merged + (size_t)i * (size_t)(C + 2);
    if (j == 0)
        *(float2*)mrow = make_float2(rs.x, rs.y);
    float2* m = (float2*)(mrow + 2 + (size_t)j * 4);
    m[0] = make_float2(f.x, f.y);
    m[1] = make_float2(f.z, f.w);
}

__global__ void feat_kernel_g(const float4* __restrict__ x_feats,
                              float4* __restrict__ pruned,
                              float4* __restrict__ scaled,
                              float* __restrict__ merged,
                              long long total, int VC, int C) {
    long long t = (long long)blockIdx.x * blockDim.x + threadIdx.x;
    if (t >= total) return;
    int i = (int)(t / VC);
    int j = (int)(t % VC);
    float4 f = x_feats[t];
    float4 rs = g_rowinfo[i];
    pruned[t] = make_float4(f.x * rs.z, f.y * rs.z, f.z * rs.z, f.w * rs.z);
    scaled[t] = make_float4(f.x * rs.w, f.y * rs.w, f.z * rs.w, f.w * rs.w);
    float* mrow = merged + (size_t)i * (size_t)(C + 2);
    if (j == 0)
        *(float2*)mrow = make_float2(rs.x, rs.y);
    float2* m = (float2*)(mrow + 2 + (size_t)j * 4);
    m[0] = make_float2(f.x, f.y);
    m[1] = make_float2(f.z, f.w);
}

// ---------------- Launch ----------------------------------------------------
extern "C" void kernel_launch(void* const* d_in, const int* in_sizes, int n_in,
                              void* d_out, int out_size) {
    const int4*   x_coords    = (const int4*)d_in[0];
    const float*  x_feats     = (const float*)d_in[1];
    const int4*   mask_coords = (const int4*)d_in[2];
    const float2* mask_scores = (const float2*)d_in[3];
    const int4*   ds_coords   = (const int4*)d_in[4];

    int N  = in_sizes[0] / 4;
    int C  = in_sizes[1] / N;
    int M  = in_sizes[2] / 4;
    int Nd = in_sizes[4] / 4;
    int VC = C / 4;

    float* out    = (float*)d_out;
    float* pruned = out;
    float* scaled = out + (size_t)N * C;
    float* merged = out + (size_t)2 * N * C;
    float* dsm    = merged + (size_t)N * (C + 2);

    const int B = 256;
    clear_all<<<592, B>>>(dsm, Nd);

    int W = (M > Nd) ? M : Nd;
    build_all<<<(W + B - 1) / B, B>>>(mask_coords, M, ds_coords, Nd);

    row_kernel<<<(N + B - 1) / B, B>>>(x_coords, mask_scores, dsm, N);

    long long total = (long long)N * VC;
    int blocks = (int)((total + B - 1) / B);
    if (VC == 16)
        feat_kernel_t<16><<<blocks, B>>>((const float4*)x_feats,
                                         (float4*)pruned, (float4*)scaled,
                                         merged, total, C);
    else
        feat_kernel_g<<<blocks, B>>>((const float4*)x_feats, (float4*)pruned,
                                     (float4*)scaled, merged, total, VC, C);
}

// round 15
// speedup vs baseline: 1.0342x; 1.0342x over previous
#include <cuda_runtime.h>
#include <stdint.h>

// =============================================================================
// key32 = int32-wrapped reference key: (b&3)<<30 | x<<20 | y<<10 | z.
// Packed hash entry (8B): key32<<32 | index. atomicMin == min-index per key.
// EMPTY 0xFF..F unreachable (key bit 29 always 0 for coords < 512).
//
// R14: R13's interleaved build kept; row kernel reverted to CONDITIONAL ds
// probe (R13's unconditional probe tripled ds-probe volume -> +4us).
// Build is per-SM atomic-issue-slot bound (~26us floor) -- no more MLP bets.
// =============================================================================

#define MASK_CAP (1u << 22)
#define DS_CAP   (1u << 19)
#define EMPTY64  0xFFFFFFFFFFFFFFFFull

__device__ unsigned long long g_mtab[MASK_CAP];
__device__ unsigned long long g_dtab[DS_CAP];
__device__ float4             g_rowinfo[1100000];   // (s0, s1, attn, attn*s1)

__device__ __forceinline__ uint32_t key32_of(int4 c) {
    return ((uint32_t)c.x << 30) | ((uint32_t)c.y << 20) |
           ((uint32_t)c.z << 10) | (uint32_t)c.w;
}

__device__ __forceinline__ uint32_t hash32(uint32_t k) {
    k ^= k >> 16; k *= 0x85ebca6bu;
    k ^= k >> 13; k *= 0xc2b2ae35u;
    k ^= k >> 16;
    return k;
}

__global__ void clear_all(float* __restrict__ dsm, int Nd) {
    int t = blockIdx.x * blockDim.x + threadIdx.x;
    int stride = gridDim.x * blockDim.x;
    ulonglong2 ff = make_ulonglong2(EMPTY64, EMPTY64);
    for (int s = t; s < (int)(MASK_CAP / 2); s += stride)
        ((ulonglong2*)g_mtab)[s] = ff;
    for (int s = t; s < (int)(DS_CAP / 2); s += stride)
        ((ulonglong2*)g_dtab)[s] = ff;
    float4 z = make_float4(0.f, 0.f, 0.f, 0.f);
    for (int s = t; s < Nd / 4; s += stride)
        ((float4*)dsm)[s] = z;
    int tail = (Nd / 4) * 4;
    if (t < Nd - tail) dsm[tail + t] = 0.f;
}

// ---------------- Build: interleaved mask+ds insert chains per thread ------
__global__ void build_all(const int4* __restrict__ mask_coords, int M,
                          const int4* __restrict__ ds_coords, int Nd) {
    int i = blockIdx.x * blockDim.x + threadIdx.x;
    bool do_m = (i < M);
    bool do_d = (i < Nd);
    uint32_t k1 = 0, k2 = 0, s1 = 0, s2 = 0;
    unsigned long long w1 = 0, w2 = 0;
    if (do_m) {
        k1 = key32_of(mask_coords[i]);
        s1 = hash32(k1) & (MASK_CAP - 1);
        w1 = ((unsigned long long)k1 << 32) | (uint32_t)i;
    }
    if (do_d) {
        k2 = key32_of(ds_coords[i]);
        s2 = hash32(k2) & (DS_CAP - 1);
        w2 = ((unsigned long long)k2 << 32) | (uint32_t)i;
    }
    while (do_m || do_d) {
        unsigned long long p1 = 0, p2 = 0;
        if (do_m) p1 = atomicCAS(&g_mtab[s1], EMPTY64, w1);
        if (do_d) p2 = atomicCAS(&g_dtab[s2], EMPTY64, w2);
        if (do_m) {
            if (p1 == EMPTY64) do_m = false;
            else if ((uint32_t)(p1 >> 32) == k1) { atomicMin(&g_mtab[s1], w1); do_m = false; }
            else s1 = (s1 + 1) & (MASK_CAP - 1);
        }
        if (do_d) {
            if (p2 == EMPTY64) do_d = false;
            else if ((uint32_t)(p2 >> 32) == k2) { atomicMin(&g_dtab[s2], w2); do_d = false; }
            else s2 = (s2 + 1) & (DS_CAP - 1);
        }
    }
}

// ---------------- Row: join + rowinfo + CONDITIONAL ds scatter -------------
__global__ void row_kernel(const int4* __restrict__ x_coords,
                           const float2* __restrict__ mask_scores,
                           float* __restrict__ ds_mask,
                           int N) {
    int i = blockIdx.x * blockDim.x + threadIdx.x;
    if (i >= N) return;
    int4 c = x_coords[i];
    uint32_t k = key32_of(c);
    float s0 = 0.0f, s1 = 0.0f;
    uint32_t slot = hash32(k) & (MASK_CAP - 1);
    while (true) {
        unsigned long long e = __ldg(&g_mtab[slot]);
        if ((uint32_t)(e >> 32) == k) {
            float2 msv = __ldg(&mask_scores[(uint32_t)e]);
            s0 = msv.x; s1 = msv.y;
            break;
        }
        if (e == EMPTY64) break;
        slot = (slot + 1) & (MASK_CAP - 1);
    }
    float attn = (s1 > 0.5f) ? 1.0f : 0.0f;
    g_rowinfo[i] = make_float4(s0, s1, attn, s1 * attn);
    if (attn > 0.0f) {
        uint32_t pk = key32_of(make_int4(c.x, c.y >> 1, c.z >> 1, c.w >> 1));
        uint32_t ds = hash32(pk) & (DS_CAP - 1);
        while (true) {
            unsigned long long e = __ldg(&g_dtab[ds]);
            if ((uint32_t)(e >> 32) == pk) { ds_mask[(uint32_t)e] = 1.0f; break; }
            if (e == EMPTY64) break;
            ds = (ds + 1) & (DS_CAP - 1);
        }
    }
}

// ---------------- Feature kernel: templated VC (shifts, no division) -------
template <int VCC>
__global__ void feat_kernel_t(const float4* __restrict__ x_feats,
                              float4* __restrict__ pruned,
                              float4* __restrict__ scaled,
                              float* __restrict__ merged,
                              long long total, int C) {
    long long t = (long long)blockIdx.x * blockDim.x + threadIdx.x;
    if (t >= total) return;
    int i = (int)(t / VCC);
    int j = (int)(t % VCC);
    float4 f = x_feats[t];
    float4 rs = g_rowinfo[i];   // (s0, s1, attn, attn*s1)
    pruned[t] = make_float4(f.x * rs.z, f.y * rs.z, f.z * rs.z, f.w * rs.z);
    scaled[t] = make_float4(f.x * rs.w, f.y * rs.w, f.z * rs.w, f.w * rs.w);
    float* mrow = merged + (size_t)i * (size_t)(C + 2);
    if (j == 0)
        *(float2*)mrow = make_float2(rs.x, rs.y);   // leader owns the line
    float2* m = (float2*)(mrow + 2 + (size_t)j * 4);
    m[0] = make_float2(f.x, f.y);
    m[1] = make_float2(f.z, f.w);
}

__global__ void feat_kernel_g(const float4* __restrict__ x_feats,
                              float4* __restrict__ pruned,
                              float4* __restrict__ scaled,
                              float* __restrict__ merged,
                              long long total, int VC, int C) {
    long long t = (long long)blockIdx.x * blockDim.x + threadIdx.x;
    if (t >= total) return;
    int i = (int)(t / VC);
    int j = (int)(t % VC);
    float4 f = x_feats[t];
    float4 rs = g_rowinfo[i];
    pruned[t] = make_float4(f.x * rs.z, f.y * rs.z, f.z * rs.z, f.w * rs.z);
    scaled[t] = make_float4(f.x * rs.w, f.y * rs.w, f.z * rs.w, f.w * rs.w);
    float* mrow = merged + (size_t)i * (size_t)(C + 2);
    if (j == 0)
        *(float2*)mrow = make_float2(rs.x, rs.y);
    float2* m = (float2*)(mrow + 2 + (size_t)j * 4);
    m[0] = make_float2(f.x, f.y);
    m[1] = make_float2(f.z, f.w);
}

// ---------------- Launch ----------------------------------------------------
extern "C" void kernel_launch(void* const* d_in, const int* in_sizes, int n_in,
                              void* d_out, int out_size) {
    const int4*   x_coords    = (const int4*)d_in[0];
    const float*  x_feats     = (const float*)d_in[1];
    const int4*   mask_coords = (const int4*)d_in[2];
    const float2* mask_scores = (const float2*)d_in[3];
    const int4*   ds_coords   = (const int4*)d_in[4];

    int N  = in_sizes[0] / 4;
    int C  = in_sizes[1] / N;
    int M  = in_sizes[2] / 4;
    int Nd = in_sizes[4] / 4;
    int VC = C / 4;

    float* out    = (float*)d_out;
    float* pruned = out;
    float* scaled = out + (size_t)N * C;
    float* merged = out + (size_t)2 * N * C;
    float* dsm    = merged + (size_t)N * (C + 2);

    const int B = 256;
    clear_all<<<592, B>>>(dsm, Nd);

    int W = (M > Nd) ? M : Nd;
    build_all<<<(W + B - 1) / B, B>>>(mask_coords, M, ds_coords, Nd);

    row_kernel<<<(N + B - 1) / B, B>>>(x_coords, mask_scores, dsm, N);

    long long total = (long long)N * VC;
    int blocks = (int)((total + B - 1) / B);
    if (VC == 16)
        feat_kernel_t<16><<<blocks, B>>>((const float4*)x_feats,
                                         (float4*)pruned, (float4*)scaled,
                                         merged, total, C);
    else
        feat_kernel_g<<<blocks, B>>>((const float4*)x_feats, (float4*)pruned,
                                     (float4*)scaled, merged, total, VC, C);
}